// round 6
// baseline (speedup 1.0000x reference)
#include <cuda_runtime.h>
#include <math.h>
#include <stdint.h>

#define NB_   7
#define S_    16
#define D_    128
#define B_    32
#define T_    2048
#define KMAX_ 31

__constant__ int c_ks[NB_] = {31, 21, 15, 11, 7, 5, 3};

// Scratch (device globals; no allocations allowed)
__device__ float g_h[(size_t)NB_ * B_ * T_ * D_];        // post-LN1 h  [nb][b][t][d]
__device__ float g_p[(size_t)B_ * T_ * NB_ * 4 * S_];    // cat layout  [b][t][nb][4S]

// Pre-rounded (tf32) weights
#define NWC (NB_ * KMAX_ * S_ * D_)      // 444416
#define NW1 (NB_ * D_ * 2 * D_)          // 229376
#define NW2 (NB_ * 2 * D_ * D_)          // 229376
#define NWP (NB_ * D_ * 64)              // 57344
#define NWM (448 * 128)                  // 57344
__device__ float g_wc[NWC];
__device__ float g_w1[NW1];
__device__ float g_w2[NW2];
__device__ float g_wp[NWP];
__device__ float g_wm[NWM];

__device__ __forceinline__ float gelu_exact(float v) {
    return 0.5f * v * (1.0f + erff(v * 0.70710678118654752440f));
}

__device__ __forceinline__ uint32_t f2tf(float f) {
    uint32_t r;
    asm("cvt.rna.tf32.f32 %0, %1;" : "=r"(r) : "f"(f));
    return r;
}

__device__ __forceinline__ void mma_tf32(float c[4],
    uint32_t a0, uint32_t a1, uint32_t a2, uint32_t a3,
    uint32_t b0, uint32_t b1)
{
    asm volatile(
        "mma.sync.aligned.m16n8k8.row.col.f32.tf32.tf32.f32 "
        "{%0,%1,%2,%3},{%4,%5,%6,%7},{%8,%9},{%0,%1,%2,%3};"
        : "+f"(c[0]), "+f"(c[1]), "+f"(c[2]), "+f"(c[3])
        : "r"(a0), "r"(a1), "r"(a2), "r"(a3), "r"(b0), "r"(b1));
}

// ---------------------------------------------------------------------------
// Kernel 0: tf32-round all GEMM weights once per launch
// ---------------------------------------------------------------------------
__global__ __launch_bounds__(256) void k_prep(
    const float* __restrict__ cw, const float* __restrict__ w1,
    const float* __restrict__ w2, const float* __restrict__ pw,
    const float* __restrict__ mw1)
{
    const int stride = gridDim.x * blockDim.x;
    int i0 = blockIdx.x * blockDim.x + threadIdx.x;
    for (int i = i0; i < NWC; i += stride) g_wc[i] = __uint_as_float(f2tf(cw[i]));
    for (int i = i0; i < NW1; i += stride) g_w1[i] = __uint_as_float(f2tf(w1[i]));
    for (int i = i0; i < NW2; i += stride) g_w2[i] = __uint_as_float(f2tf(w2[i]));
    for (int i = i0; i < NWP; i += stride) g_wp[i] = __uint_as_float(f2tf(pw[i]));
    for (int i = i0; i < NWM; i += stride) g_wm[i] = __uint_as_float(f2tf(mw1[i]));
}

// ---------------------------------------------------------------------------
// Kernel 1 (tensor-core): implicit-GEMM conv (masked taps) + bias + LN -> g_h
// grid (T/64, B, NB), block 256 (8 warps). out[64,128] per block.
// ---------------------------------------------------------------------------
#define XSTR 20
#define HP   132
#define CMT  4      // 64 tokens = 4 m-tiles

__global__ __launch_bounds__(256) void k_conv_tc(
    const float* __restrict__ x,
    const float* __restrict__ conv_b, const float* __restrict__ dec_g,
    const float* __restrict__ dec_b)
{
    __shared__ float xs[(64 + KMAX_ - 1) * XSTR];   // 94 rows x stride 20
    __shared__ float hs[64 * HP];

    const int band = blockIdx.z, b = blockIdx.y;
    const int t0 = blockIdx.x * 64;
    const int tid = threadIdx.x;
    const int warp = tid >> 5, lane = tid & 31;
    const int grp = lane >> 2, tig = lane & 3;

    // stage x window rows [t0-15, t0+78], tf32-rounded
    const float* xb = x + (size_t)b * T_ * S_;
    for (int i = tid; i < 94 * S_; i += 256) {
        int row = i >> 4, s = i & 15;
        int gt = t0 + row - (KMAX_ / 2);
        float v = (gt >= 0 && gt < T_) ? xb[gt * S_ + s] : 0.0f;
        xs[row * XSTR + s] = __uint_as_float(f2tf(v));
    }
    __syncthreads();

    float acc[CMT][2][4];
#pragma unroll
    for (int mt = 0; mt < CMT; ++mt)
#pragma unroll
        for (int nt = 0; nt < 2; ++nt)
#pragma unroll
            for (int c = 0; c < 4; ++c) acc[mt][nt][c] = 0.0f;

    const int Kb = c_ks[band];
    const int off = (KMAX_ - Kb) >> 1;
    const float* wb = g_wc + (size_t)band * KMAX_ * S_ * D_;

    for (int k = off; k < off + Kb; ++k) {
#pragma unroll
        for (int c8 = 0; c8 < 2; ++c8) {
            const int s0 = c8 * 8;
            uint32_t a[CMT][4];
#pragma unroll
            for (int mt = 0; mt < CMT; ++mt) {
                int r0 = mt * 16 + grp + k;
                a[mt][0] = __float_as_uint(xs[r0 * XSTR + s0 + tig]);
                a[mt][1] = __float_as_uint(xs[(r0 + 8) * XSTR + s0 + tig]);
                a[mt][2] = __float_as_uint(xs[r0 * XSTR + s0 + tig + 4]);
                a[mt][3] = __float_as_uint(xs[(r0 + 8) * XSTR + s0 + tig + 4]);
            }
#pragma unroll
            for (int nt = 0; nt < 2; ++nt) {
                int col = warp * 16 + nt * 8 + grp;
                uint32_t bf0 = __float_as_uint(wb[(size_t)(k * S_ + s0 + tig) * D_ + col]);
                uint32_t bf1 = __float_as_uint(wb[(size_t)(k * S_ + s0 + tig + 4) * D_ + col]);
#pragma unroll
                for (int mt = 0; mt < CMT; ++mt)
                    mma_tf32(acc[mt][nt], a[mt][0], a[mt][1], a[mt][2], a[mt][3], bf0, bf1);
            }
        }
    }

    // bias -> hs
#pragma unroll
    for (int nt = 0; nt < 2; ++nt) {
        int col0 = warp * 16 + nt * 8 + tig * 2;
        float bb0 = conv_b[band * D_ + col0];
        float bb1 = conv_b[band * D_ + col0 + 1];
#pragma unroll
        for (int mt = 0; mt < CMT; ++mt) {
            int r0 = mt * 16 + grp;
            hs[r0 * HP + col0]           = acc[mt][nt][0] + bb0;
            hs[r0 * HP + col0 + 1]       = acc[mt][nt][1] + bb1;
            hs[(r0 + 8) * HP + col0]     = acc[mt][nt][2] + bb0;
            hs[(r0 + 8) * HP + col0 + 1] = acc[mt][nt][3] + bb1;
        }
    }
    __syncthreads();

    // LayerNorm (8 warps x 8 tokens) -> g_h
    {
        float gv[4], bv[4];
#pragma unroll
        for (int c = 0; c < 4; ++c) {
            gv[c] = dec_g[band * D_ + lane + 32 * c];
            bv[c] = dec_b[band * D_ + lane + 32 * c];
        }
        float* hb = g_h + (((size_t)band * B_ + b) * T_ + t0) * D_;
        for (int i = 0; i < 8; ++i) {
            int tt = warp * 8 + i;
            float v[4]; float s = 0.0f;
#pragma unroll
            for (int c = 0; c < 4; ++c) { v[c] = hs[tt * HP + lane + 32 * c]; s += v[c]; }
#pragma unroll
            for (int o = 16; o; o >>= 1) s += __shfl_xor_sync(0xffffffffu, s, o);
            float mean = s * (1.0f / 128.0f);
            float q = 0.0f;
#pragma unroll
            for (int c = 0; c < 4; ++c) { float d0 = v[c] - mean; q = fmaf(d0, d0, q); }
#pragma unroll
            for (int o = 16; o; o >>= 1) q += __shfl_xor_sync(0xffffffffu, q, o);
            float rstd = rsqrtf(q * (1.0f / 128.0f) + 1e-5f);
#pragma unroll
            for (int c = 0; c < 4; ++c)
                hb[(size_t)tt * D_ + lane + 32 * c] = (v[c] - mean) * rstd * gv[c] + bv[c];
        }
    }
}

// ---------------------------------------------------------------------------
// Kernel 2 (tensor-core, 64-token tile, no hs buffer => 100KB smem, 2 CTA/SM):
// LN2 -> GEMM1(gelu) -> GEMM2(+h from gmem) -> proj -> g_p
// ---------------------------------------------------------------------------
#define ZP 132
#define UP 260
#define MT 4

__global__ __launch_bounds__(256) void k_ffn_tc(
    const float* __restrict__ n2_g, const float* __restrict__ n2_b,
    const float* __restrict__ fb1,
    const float* __restrict__ fb2,
    const float* __restrict__ pb)
{
    extern __shared__ float sm[];
    float* zs = sm;                 // 64*132
    float* us = sm + 64 * ZP;       // 64*260

    const int band = blockIdx.z, b = blockIdx.y;
    const int t0 = blockIdx.x * 64;
    const int tid = threadIdx.x;
    const int warp = tid >> 5, lane = tid & 31;
    const int grp = lane >> 2, tig = lane & 3;

    const float* hbp = g_h + (((size_t)band * B_ + b) * T_ + t0) * 128;

    // LN2 straight from gmem: warp handles 8 tokens -> zs (tf32-rounded)
    {
        float gv[4], bv[4];
#pragma unroll
        for (int c = 0; c < 4; ++c) {
            gv[c] = n2_g[band * 128 + lane + 32 * c];
            bv[c] = n2_b[band * 128 + lane + 32 * c];
        }
        for (int i = 0; i < 8; ++i) {
            int tt = warp * 8 + i;
            float v[4]; float s = 0.0f;
#pragma unroll
            for (int c = 0; c < 4; ++c) { v[c] = hbp[tt * 128 + lane + 32 * c]; s += v[c]; }
#pragma unroll
            for (int o = 16; o; o >>= 1) s += __shfl_xor_sync(0xffffffffu, s, o);
            float mean = s * (1.0f / 128.0f);
            float q = 0.0f;
#pragma unroll
            for (int c = 0; c < 4; ++c) { float d0 = v[c] - mean; q = fmaf(d0, d0, q); }
#pragma unroll
            for (int o = 16; o; o >>= 1) q += __shfl_xor_sync(0xffffffffu, q, o);
            float rstd = rsqrtf(q * (1.0f / 128.0f) + 1e-5f);
#pragma unroll
            for (int c = 0; c < 4; ++c) {
                float zv = (v[c] - mean) * rstd * gv[c] + bv[c];
                zs[tt * ZP + lane + 32 * c] = __uint_as_float(f2tf(zv));
            }
        }
    }
    __syncthreads();

    // GEMM1: u = gelu(z[64,128] @ W1[128,256] + b1). warp n-slice 32 wide.
    {
        float acc[MT][4][4];
#pragma unroll
        for (int mt = 0; mt < MT; ++mt)
#pragma unroll
            for (int nt = 0; nt < 4; ++nt)
#pragma unroll
                for (int c = 0; c < 4; ++c) acc[mt][nt][c] = 0.0f;

        const float* w1g = g_w1 + (size_t)band * 128 * 256;
        for (int k0 = 0; k0 < 128; k0 += 8) {
            uint32_t a[MT][4];
#pragma unroll
            for (int mt = 0; mt < MT; ++mt) {
                int r0 = mt * 16 + grp;
                a[mt][0] = __float_as_uint(zs[r0 * ZP + k0 + tig]);
                a[mt][1] = __float_as_uint(zs[(r0 + 8) * ZP + k0 + tig]);
                a[mt][2] = __float_as_uint(zs[r0 * ZP + k0 + tig + 4]);
                a[mt][3] = __float_as_uint(zs[(r0 + 8) * ZP + k0 + tig + 4]);
            }
#pragma unroll
            for (int nt = 0; nt < 4; ++nt) {
                int col = warp * 32 + nt * 8 + grp;
                uint32_t bf0 = __float_as_uint(w1g[(k0 + tig) * 256 + col]);
                uint32_t bf1 = __float_as_uint(w1g[(k0 + tig + 4) * 256 + col]);
#pragma unroll
                for (int mt = 0; mt < MT; ++mt)
                    mma_tf32(acc[mt][nt], a[mt][0], a[mt][1], a[mt][2], a[mt][3], bf0, bf1);
            }
        }
#pragma unroll
        for (int nt = 0; nt < 4; ++nt) {
            int col0 = warp * 32 + nt * 8 + tig * 2;
            float bb0 = fb1[band * 256 + col0];
            float bb1 = fb1[band * 256 + col0 + 1];
#pragma unroll
            for (int mt = 0; mt < MT; ++mt) {
                int r0 = mt * 16 + grp;
                us[r0 * UP + col0]           = __uint_as_float(f2tf(gelu_exact(acc[mt][nt][0] + bb0)));
                us[r0 * UP + col0 + 1]       = __uint_as_float(f2tf(gelu_exact(acc[mt][nt][1] + bb1)));
                us[(r0 + 8) * UP + col0]     = __uint_as_float(f2tf(gelu_exact(acc[mt][nt][2] + bb0)));
                us[(r0 + 8) * UP + col0 + 1] = __uint_as_float(f2tf(gelu_exact(acc[mt][nt][3] + bb1)));
            }
        }
    }
    __syncthreads();

    // GEMM2: band_out = h(gmem) + u[64,256] @ W2[256,128] + b2. warp n-slice 16.
    {
        float acc[MT][2][4];
#pragma unroll
        for (int mt = 0; mt < MT; ++mt)
#pragma unroll
            for (int nt = 0; nt < 2; ++nt)
#pragma unroll
                for (int c = 0; c < 4; ++c) acc[mt][nt][c] = 0.0f;

        const float* w2g = g_w2 + (size_t)band * 256 * 128;
        for (int k0 = 0; k0 < 256; k0 += 8) {
            uint32_t a[MT][4];
#pragma unroll
            for (int mt = 0; mt < MT; ++mt) {
                int r0 = mt * 16 + grp;
                a[mt][0] = __float_as_uint(us[r0 * UP + k0 + tig]);
                a[mt][1] = __float_as_uint(us[(r0 + 8) * UP + k0 + tig]);
                a[mt][2] = __float_as_uint(us[r0 * UP + k0 + tig + 4]);
                a[mt][3] = __float_as_uint(us[(r0 + 8) * UP + k0 + tig + 4]);
            }
#pragma unroll
            for (int nt = 0; nt < 2; ++nt) {
                int col = warp * 16 + nt * 8 + grp;
                uint32_t bf0 = __float_as_uint(w2g[(k0 + tig) * 128 + col]);
                uint32_t bf1 = __float_as_uint(w2g[(k0 + tig + 4) * 128 + col]);
#pragma unroll
                for (int mt = 0; mt < MT; ++mt)
                    mma_tf32(acc[mt][nt], a[mt][0], a[mt][1], a[mt][2], a[mt][3], bf0, bf1);
            }
        }
        __syncthreads();   // us done; zs about to be overwritten
#pragma unroll
        for (int nt = 0; nt < 2; ++nt) {
            int col0 = warp * 16 + nt * 8 + tig * 2;
            float bb0 = fb2[band * 128 + col0];
            float bb1 = fb2[band * 128 + col0 + 1];
#pragma unroll
            for (int mt = 0; mt < MT; ++mt) {
                int r0 = mt * 16 + grp;
                float2 h00 = *(const float2*)&hbp[r0 * 128 + col0];
                float2 h08 = *(const float2*)&hbp[(r0 + 8) * 128 + col0];
                zs[r0 * ZP + col0]           = __uint_as_float(f2tf(acc[mt][nt][0] + bb0 + h00.x));
                zs[r0 * ZP + col0 + 1]       = __uint_as_float(f2tf(acc[mt][nt][1] + bb1 + h00.y));
                zs[(r0 + 8) * ZP + col0]     = __uint_as_float(f2tf(acc[mt][nt][2] + bb0 + h08.x));
                zs[(r0 + 8) * ZP + col0 + 1] = __uint_as_float(f2tf(acc[mt][nt][3] + bb1 + h08.y));
            }
        }
    }
    __syncthreads();

    // proj: p = band_out[64,128] @ pw[128,64] + pb -> g_p. warp n-slice 8.
    {
        float acc[MT][4];
#pragma unroll
        for (int mt = 0; mt < MT; ++mt)
#pragma unroll
            for (int c = 0; c < 4; ++c) acc[mt][c] = 0.0f;

        const float* pwg = g_wp + (size_t)band * 128 * 64;
        for (int k0 = 0; k0 < 128; k0 += 8) {
            uint32_t a[MT][4];
#pragma unroll
            for (int mt = 0; mt < MT; ++mt) {
                int r0 = mt * 16 + grp;
                a[mt][0] = __float_as_uint(zs[r0 * ZP + k0 + tig]);
                a[mt][1] = __float_as_uint(zs[(r0 + 8) * ZP + k0 + tig]);
                a[mt][2] = __float_as_uint(zs[r0 * ZP + k0 + tig + 4]);
                a[mt][3] = __float_as_uint(zs[(r0 + 8) * ZP + k0 + tig + 4]);
            }
            int col = warp * 8 + grp;
            uint32_t bf0 = __float_as_uint(pwg[(k0 + tig) * 64 + col]);
            uint32_t bf1 = __float_as_uint(pwg[(k0 + tig + 4) * 64 + col]);
#pragma unroll
            for (int mt = 0; mt < MT; ++mt)
                mma_tf32(acc[mt], a[mt][0], a[mt][1], a[mt][2], a[mt][3], bf0, bf1);
        }
        int col0 = warp * 8 + tig * 2;
        float bb0 = pb[band * 64 + col0];
        float bb1 = pb[band * 64 + col0 + 1];
#pragma unroll
        for (int mt = 0; mt < MT; ++mt) {
            int r0 = mt * 16 + grp;
            float2 v0 = make_float2(acc[mt][0] + bb0, acc[mt][1] + bb1);
            float2 v1 = make_float2(acc[mt][2] + bb0, acc[mt][3] + bb1);
            *(float2*)&g_p[(((size_t)b * T_ + t0 + r0) * NB_ + band) * 64 + col0] = v0;
            *(float2*)&g_p[(((size_t)b * T_ + t0 + r0 + 8) * NB_ + band) * 64 + col0] = v1;
        }
    }
}

// ---------------------------------------------------------------------------
// Kernel 3 (tensor-core GEMM1): cat[32,448] @ mix_w1[448,128] -> gelu -> ms
// then fp32 FFMA 128->16. grid (B*T/32), block 256.
// ---------------------------------------------------------------------------
#define CP 452
#define MP 132

__global__ __launch_bounds__(256) void k_mix_tc(
    const float* __restrict__ mb1,
    const float* __restrict__ mw2, const float* __restrict__ mb2,
    float* __restrict__ out)
{
    extern __shared__ float sm[];
    float* cs = sm;                 // 32*452
    float* ms = sm + 32 * CP;       // 32*132

    const int bt0 = blockIdx.x * 32;
    const int tid = threadIdx.x;
    const int warp = tid >> 5, lane = tid & 31;
    const int grp = lane >> 2, tig = lane & 3;

    const float* cb = g_p + (size_t)bt0 * 448;
    for (int i = tid; i < 32 * 448; i += 256) {
        int r = i / 448, c = i - r * 448;
        cs[r * CP + c] = __uint_as_float(f2tf(cb[i]));
    }
    __syncthreads();

    {
        float acc[2][2][4];
#pragma unroll
        for (int mt = 0; mt < 2; ++mt)
#pragma unroll
            for (int nt = 0; nt < 2; ++nt)
#pragma unroll
                for (int c = 0; c < 4; ++c) acc[mt][nt][c] = 0.0f;

        for (int k0 = 0; k0 < 448; k0 += 8) {
            uint32_t a[2][4];
#pragma unroll
            for (int mt = 0; mt < 2; ++mt) {
                int r0 = mt * 16 + grp;
                a[mt][0] = __float_as_uint(cs[r0 * CP + k0 + tig]);
                a[mt][1] = __float_as_uint(cs[(r0 + 8) * CP + k0 + tig]);
                a[mt][2] = __float_as_uint(cs[r0 * CP + k0 + tig + 4]);
                a[mt][3] = __float_as_uint(cs[(r0 + 8) * CP + k0 + tig + 4]);
            }
#pragma unroll
            for (int nt = 0; nt < 2; ++nt) {
                int col = warp * 16 + nt * 8 + grp;
                uint32_t bf0 = __float_as_uint(g_wm[(k0 + tig) * 128 + col]);
                uint32_t bf1 = __float_as_uint(g_wm[(k0 + tig + 4) * 128 + col]);
#pragma unroll
                for (int mt = 0; mt < 2; ++mt)
                    mma_tf32(acc[mt][nt], a[mt][0], a[mt][1], a[mt][2], a[mt][3], bf0, bf1);
            }
        }
#pragma unroll
        for (int nt = 0; nt < 2; ++nt) {
            int col0 = warp * 16 + nt * 8 + tig * 2;
            float bb0 = mb1[col0];
            float bb1 = mb1[col0 + 1];
#pragma unroll
            for (int mt = 0; mt < 2; ++mt) {
                int r0 = mt * 16 + grp;
                ms[r0 * MP + col0]           = gelu_exact(acc[mt][nt][0] + bb0);
                ms[r0 * MP + col0 + 1]       = gelu_exact(acc[mt][nt][1] + bb1);
                ms[(r0 + 8) * MP + col0]     = gelu_exact(acc[mt][nt][2] + bb0);
                ms[(r0 + 8) * MP + col0 + 1] = gelu_exact(acc[mt][nt][3] + bb1);
            }
        }
    }
    __syncthreads();

    {
        const int o = tid & 15, tb = tid >> 4;
        const float* wc = mw2 + o;
        const float bo = mb2[o];
#pragma unroll
        for (int h = 0; h < 2; ++h) {
            int tt = tb + h * 16;
            float acc = 0.0f;
            for (int e = 0; e < 128; e += 4) {
                float4 mv = *(const float4*)&ms[tt * MP + e];
                acc = fmaf(mv.x, wc[(e + 0) * 16], acc);
                acc = fmaf(mv.y, wc[(e + 1) * 16], acc);
                acc = fmaf(mv.z, wc[(e + 2) * 16], acc);
                acc = fmaf(mv.w, wc[(e + 3) * 16], acc);
            }
            out[(size_t)(bt0 + tt) * 16 + o] = acc + bo;
        }
    }
}

// ---------------------------------------------------------------------------
extern "C" void kernel_launch(void* const* d_in, const int* in_sizes, int n_in,
                              void* d_out, int out_size)
{
    const float* x      = (const float*)d_in[0];
    const float* conv_w = (const float*)d_in[1];
    const float* conv_b = (const float*)d_in[2];
    const float* dec_g  = (const float*)d_in[3];
    const float* dec_b  = (const float*)d_in[4];
    const float* n2_g   = (const float*)d_in[5];
    const float* n2_b   = (const float*)d_in[6];
    const float* ffn_w1 = (const float*)d_in[7];
    const float* ffn_b1 = (const float*)d_in[8];
    const float* ffn_w2 = (const float*)d_in[9];
    const float* ffn_b2 = (const float*)d_in[10];
    const float* proj_w = (const float*)d_in[11];
    const float* proj_b = (const float*)d_in[12];
    const float* mix_w1 = (const float*)d_in[13];
    const float* mix_b1 = (const float*)d_in[14];
    const float* mix_w2 = (const float*)d_in[15];
    const float* mix_b2 = (const float*)d_in[16];
    float* out = (float*)d_out;

    const int smem_ffn = 64 * (ZP + UP) * 4;                // 100352 B
    const int smem_mix = (32 * CP + 32 * MP) * 4;           // 74752 B
    cudaFuncSetAttribute(k_ffn_tc, cudaFuncAttributeMaxDynamicSharedMemorySize, smem_ffn);
    cudaFuncSetAttribute(k_mix_tc, cudaFuncAttributeMaxDynamicSharedMemorySize, smem_mix);

    k_prep<<<512, 256>>>(conv_w, ffn_w1, ffn_w2, proj_w, mix_w1);

    dim3 g1(T_ / 64, B_, NB_);
    k_conv_tc<<<g1, 256>>>(x, conv_b, dec_g, dec_b);

    dim3 g2(T_ / 64, B_, NB_);
    k_ffn_tc<<<g2, 256, smem_ffn>>>(n2_g, n2_b, ffn_b1, ffn_b2, proj_b);

    dim3 g3((B_ * T_) / 32);
    k_mix_tc<<<g3, 256, smem_mix>>>(mix_b1, mix_w2, mix_b2, out);
}

// round 7
// speedup vs baseline: 1.2609x; 1.2609x over previous
#include <cuda_runtime.h>
#include <math.h>
#include <stdint.h>

#define NB_   7
#define S_    16
#define D_    128
#define B_    32
#define T_    2048
#define KMAX_ 31

__constant__ int c_ks[NB_] = {31, 21, 15, 11, 7, 5, 3};

// Scratch (device globals; no allocations allowed)
__device__ float g_h[(size_t)NB_ * B_ * T_ * D_];        // post-LN1 h  [nb][b][t][d]
__device__ float g_p[(size_t)B_ * T_ * NB_ * 4 * S_];    // cat layout  [b][t][nb][4S]

// Pre-rounded (tf32) weights
#define NWC (NB_ * KMAX_ * S_ * D_)      // 444416
#define NW1 (NB_ * D_ * 2 * D_)          // 229376
#define NW2 (NB_ * 2 * D_ * D_)          // 229376
#define NWP (NB_ * D_ * 64)              // 57344
#define NWM (448 * 128)                  // 57344
__device__ float g_wc[NWC];
__device__ float g_w1[NW1];
__device__ float g_w2[NW2];
__device__ float g_wp[NWP];
__device__ float g_wm[NWM];

__device__ __forceinline__ float gelu_exact(float v) {
    return 0.5f * v * (1.0f + erff(v * 0.70710678118654752440f));
}

__device__ __forceinline__ uint32_t f2tf(float f) {
    uint32_t r;
    asm("cvt.rna.tf32.f32 %0, %1;" : "=r"(r) : "f"(f));
    return r;
}

__device__ __forceinline__ void mma_tf32(float c[4],
    uint32_t a0, uint32_t a1, uint32_t a2, uint32_t a3,
    uint32_t b0, uint32_t b1)
{
    asm volatile(
        "mma.sync.aligned.m16n8k8.row.col.f32.tf32.tf32.f32 "
        "{%0,%1,%2,%3},{%4,%5,%6,%7},{%8,%9},{%0,%1,%2,%3};"
        : "+f"(c[0]), "+f"(c[1]), "+f"(c[2]), "+f"(c[3])
        : "r"(a0), "r"(a1), "r"(a2), "r"(a3), "r"(b0), "r"(b1));
}

// weight load: non-coherent path, bit pattern already tf32
__device__ __forceinline__ uint32_t wld(const float* p) {
    return __float_as_uint(__ldg(p));
}

// ---------------------------------------------------------------------------
// Kernel 0: tf32-round all GEMM weights once per launch
// ---------------------------------------------------------------------------
__global__ __launch_bounds__(256) void k_prep(
    const float* __restrict__ cw, const float* __restrict__ w1,
    const float* __restrict__ w2, const float* __restrict__ pw,
    const float* __restrict__ mw1)
{
    const int stride = gridDim.x * blockDim.x;
    int i0 = blockIdx.x * blockDim.x + threadIdx.x;
    for (int i = i0; i < NWC; i += stride) g_wc[i] = __uint_as_float(f2tf(cw[i]));
    for (int i = i0; i < NW1; i += stride) g_w1[i] = __uint_as_float(f2tf(w1[i]));
    for (int i = i0; i < NW2; i += stride) g_w2[i] = __uint_as_float(f2tf(w2[i]));
    for (int i = i0; i < NWP; i += stride) g_wp[i] = __uint_as_float(f2tf(pw[i]));
    for (int i = i0; i < NWM; i += stride) g_wm[i] = __uint_as_float(f2tf(mw1[i]));
}

// ---------------------------------------------------------------------------
// Kernel 1 (tensor-core): implicit-GEMM conv (masked taps) + bias + LN -> g_h
// grid (T/32, B, NB), block 256 (8 warps). out[32,128] per block. [R4-proven]
// ---------------------------------------------------------------------------
#define XSTR 20
#define HP   132

__global__ __launch_bounds__(256) void k_conv_tc(
    const float* __restrict__ x,
    const float* __restrict__ conv_b, const float* __restrict__ dec_g,
    const float* __restrict__ dec_b)
{
    __shared__ float xs[(32 + KMAX_ - 1) * XSTR];   // 62 rows x stride 20
    __shared__ float hs[32 * HP];

    const int band = blockIdx.z, b = blockIdx.y;
    const int t0 = blockIdx.x * 32;
    const int tid = threadIdx.x;
    const int warp = tid >> 5, lane = tid & 31;
    const int grp = lane >> 2, tig = lane & 3;

    const float* xb = x + (size_t)b * T_ * S_;
    for (int i = tid; i < 62 * S_; i += 256) {
        int row = i >> 4, s = i & 15;
        int gt = t0 + row - (KMAX_ / 2);
        float v = (gt >= 0 && gt < T_) ? xb[gt * S_ + s] : 0.0f;
        xs[row * XSTR + s] = __uint_as_float(f2tf(v));
    }
    __syncthreads();

    float acc[2][2][4];
#pragma unroll
    for (int mt = 0; mt < 2; ++mt)
#pragma unroll
        for (int nt = 0; nt < 2; ++nt)
#pragma unroll
            for (int c = 0; c < 4; ++c) acc[mt][nt][c] = 0.0f;

    const int Kb = c_ks[band];
    const int off = (KMAX_ - Kb) >> 1;
    const float* wb = g_wc + (size_t)band * KMAX_ * S_ * D_;

    for (int k = off; k < off + Kb; ++k) {
#pragma unroll
        for (int c8 = 0; c8 < 2; ++c8) {
            const int s0 = c8 * 8;
            uint32_t a[2][4];
#pragma unroll
            for (int mt = 0; mt < 2; ++mt) {
                int r0 = mt * 16 + grp + k;
                a[mt][0] = __float_as_uint(xs[r0 * XSTR + s0 + tig]);
                a[mt][1] = __float_as_uint(xs[(r0 + 8) * XSTR + s0 + tig]);
                a[mt][2] = __float_as_uint(xs[r0 * XSTR + s0 + tig + 4]);
                a[mt][3] = __float_as_uint(xs[(r0 + 8) * XSTR + s0 + tig + 4]);
            }
#pragma unroll
            for (int nt = 0; nt < 2; ++nt) {
                int col = warp * 16 + nt * 8 + grp;
                uint32_t bf0 = wld(&wb[(size_t)(k * S_ + s0 + tig) * D_ + col]);
                uint32_t bf1 = wld(&wb[(size_t)(k * S_ + s0 + tig + 4) * D_ + col]);
#pragma unroll
                for (int mt = 0; mt < 2; ++mt)
                    mma_tf32(acc[mt][nt], a[mt][0], a[mt][1], a[mt][2], a[mt][3], bf0, bf1);
            }
        }
    }

    // bias -> hs
#pragma unroll
    for (int nt = 0; nt < 2; ++nt) {
        int col0 = warp * 16 + nt * 8 + tig * 2;
        float bb0 = conv_b[band * D_ + col0];
        float bb1 = conv_b[band * D_ + col0 + 1];
#pragma unroll
        for (int mt = 0; mt < 2; ++mt) {
            int r0 = mt * 16 + grp;
            hs[r0 * HP + col0]           = acc[mt][nt][0] + bb0;
            hs[r0 * HP + col0 + 1]       = acc[mt][nt][1] + bb1;
            hs[(r0 + 8) * HP + col0]     = acc[mt][nt][2] + bb0;
            hs[(r0 + 8) * HP + col0 + 1] = acc[mt][nt][3] + bb1;
        }
    }
    __syncthreads();

    // LayerNorm (8 warps x 4 tokens) -> g_h
    {
        float gv[4], bv[4];
#pragma unroll
        for (int c = 0; c < 4; ++c) {
            gv[c] = dec_g[band * D_ + lane + 32 * c];
            bv[c] = dec_b[band * D_ + lane + 32 * c];
        }
        float* hb = g_h + (((size_t)band * B_ + b) * T_ + t0) * D_;
        for (int i = 0; i < 4; ++i) {
            int tt = warp * 4 + i;
            float v[4]; float s = 0.0f;
#pragma unroll
            for (int c = 0; c < 4; ++c) { v[c] = hs[tt * HP + lane + 32 * c]; s += v[c]; }
#pragma unroll
            for (int o = 16; o; o >>= 1) s += __shfl_xor_sync(0xffffffffu, s, o);
            float mean = s * (1.0f / 128.0f);
            float q = 0.0f;
#pragma unroll
            for (int c = 0; c < 4; ++c) { float d0 = v[c] - mean; q = fmaf(d0, d0, q); }
#pragma unroll
            for (int o = 16; o; o >>= 1) q += __shfl_xor_sync(0xffffffffu, q, o);
            float rstd = rsqrtf(q * (1.0f / 128.0f) + 1e-5f);
#pragma unroll
            for (int c = 0; c < 4; ++c)
                hb[(size_t)tt * D_ + lane + 32 * c] = (v[c] - mean) * rstd * gv[c] + bv[c];
        }
    }
}

// ---------------------------------------------------------------------------
// Kernel 2 (tensor-core, 32-token tile, 67KB smem => 3 CTA/SM) [R2-proven]:
// LN2 -> GEMM1(gelu) -> GEMM2(+h smem) -> proj -> g_p
// ---------------------------------------------------------------------------
#define ZP 132
#define UP 260

__global__ __launch_bounds__(256) void k_ffn_tc(
    const float* __restrict__ n2_g, const float* __restrict__ n2_b,
    const float* __restrict__ fb1,
    const float* __restrict__ fb2,
    const float* __restrict__ pb)
{
    extern __shared__ float sm[];
    float* hs = sm;                 // 32*132
    float* zs = sm + 32 * ZP;       // 32*132
    float* us = zs + 32 * ZP;       // 32*260

    const int band = blockIdx.z, b = blockIdx.y;
    const int t0 = blockIdx.x * 32;
    const int tid = threadIdx.x;
    const int warp = tid >> 5, lane = tid & 31;
    const int grp = lane >> 2, tig = lane & 3;

    const float* hbp = g_h + (((size_t)band * B_ + b) * T_ + t0) * 128;
    for (int i = tid; i < 32 * 128; i += 256) {
        int r = i >> 7, c = i & 127;
        hs[r * ZP + c] = hbp[i];
    }
    __syncthreads();

    // LN2: warp handles 4 tokens -> zs (tf32-rounded)
    {
        float gv[4], bv[4];
#pragma unroll
        for (int c = 0; c < 4; ++c) {
            gv[c] = n2_g[band * 128 + lane + 32 * c];
            bv[c] = n2_b[band * 128 + lane + 32 * c];
        }
        for (int i = 0; i < 4; ++i) {
            int tt = warp * 4 + i;
            float v[4]; float s = 0.0f;
#pragma unroll
            for (int c = 0; c < 4; ++c) { v[c] = hs[tt * ZP + lane + 32 * c]; s += v[c]; }
#pragma unroll
            for (int o = 16; o; o >>= 1) s += __shfl_xor_sync(0xffffffffu, s, o);
            float mean = s * (1.0f / 128.0f);
            float q = 0.0f;
#pragma unroll
            for (int c = 0; c < 4; ++c) { float d0 = v[c] - mean; q = fmaf(d0, d0, q); }
#pragma unroll
            for (int o = 16; o; o >>= 1) q += __shfl_xor_sync(0xffffffffu, q, o);
            float rstd = rsqrtf(q * (1.0f / 128.0f) + 1e-5f);
#pragma unroll
            for (int c = 0; c < 4; ++c) {
                float zv = (v[c] - mean) * rstd * gv[c] + bv[c];
                zs[tt * ZP + lane + 32 * c] = __uint_as_float(f2tf(zv));
            }
        }
    }
    __syncthreads();

    // GEMM1: u = gelu(z[32,128] @ W1[128,256] + b1). warp n-slice 32 wide.
    {
        float acc[2][4][4];
#pragma unroll
        for (int mt = 0; mt < 2; ++mt)
#pragma unroll
            for (int nt = 0; nt < 4; ++nt)
#pragma unroll
                for (int c = 0; c < 4; ++c) acc[mt][nt][c] = 0.0f;

        const float* w1g = g_w1 + (size_t)band * 128 * 256;
        for (int k0 = 0; k0 < 128; k0 += 8) {
            uint32_t a[2][4];
#pragma unroll
            for (int mt = 0; mt < 2; ++mt) {
                int r0 = mt * 16 + grp;
                a[mt][0] = __float_as_uint(zs[r0 * ZP + k0 + tig]);
                a[mt][1] = __float_as_uint(zs[(r0 + 8) * ZP + k0 + tig]);
                a[mt][2] = __float_as_uint(zs[r0 * ZP + k0 + tig + 4]);
                a[mt][3] = __float_as_uint(zs[(r0 + 8) * ZP + k0 + tig + 4]);
            }
#pragma unroll
            for (int nt = 0; nt < 4; ++nt) {
                int col = warp * 32 + nt * 8 + grp;
                uint32_t bf0 = wld(&w1g[(k0 + tig) * 256 + col]);
                uint32_t bf1 = wld(&w1g[(k0 + tig + 4) * 256 + col]);
#pragma unroll
                for (int mt = 0; mt < 2; ++mt)
                    mma_tf32(acc[mt][nt], a[mt][0], a[mt][1], a[mt][2], a[mt][3], bf0, bf1);
            }
        }
#pragma unroll
        for (int nt = 0; nt < 4; ++nt) {
            int col0 = warp * 32 + nt * 8 + tig * 2;
            float bb0 = fb1[band * 256 + col0];
            float bb1 = fb1[band * 256 + col0 + 1];
#pragma unroll
            for (int mt = 0; mt < 2; ++mt) {
                int r0 = mt * 16 + grp;
                us[r0 * UP + col0]           = __uint_as_float(f2tf(gelu_exact(acc[mt][nt][0] + bb0)));
                us[r0 * UP + col0 + 1]       = __uint_as_float(f2tf(gelu_exact(acc[mt][nt][1] + bb1)));
                us[(r0 + 8) * UP + col0]     = __uint_as_float(f2tf(gelu_exact(acc[mt][nt][2] + bb0)));
                us[(r0 + 8) * UP + col0 + 1] = __uint_as_float(f2tf(gelu_exact(acc[mt][nt][3] + bb1)));
            }
        }
    }
    __syncthreads();

    // GEMM2: band_out = h + u[32,256] @ W2[256,128] + b2. warp n-slice 16.
    {
        float acc[2][2][4];
#pragma unroll
        for (int mt = 0; mt < 2; ++mt)
#pragma unroll
            for (int nt = 0; nt < 2; ++nt)
#pragma unroll
                for (int c = 0; c < 4; ++c) acc[mt][nt][c] = 0.0f;

        const float* w2g = g_w2 + (size_t)band * 256 * 128;
        for (int k0 = 0; k0 < 256; k0 += 8) {
            uint32_t a[2][4];
#pragma unroll
            for (int mt = 0; mt < 2; ++mt) {
                int r0 = mt * 16 + grp;
                a[mt][0] = __float_as_uint(us[r0 * UP + k0 + tig]);
                a[mt][1] = __float_as_uint(us[(r0 + 8) * UP + k0 + tig]);
                a[mt][2] = __float_as_uint(us[r0 * UP + k0 + tig + 4]);
                a[mt][3] = __float_as_uint(us[(r0 + 8) * UP + k0 + tig + 4]);
            }
#pragma unroll
            for (int nt = 0; nt < 2; ++nt) {
                int col = warp * 16 + nt * 8 + grp;
                uint32_t bf0 = wld(&w2g[(k0 + tig) * 128 + col]);
                uint32_t bf1 = wld(&w2g[(k0 + tig + 4) * 128 + col]);
#pragma unroll
                for (int mt = 0; mt < 2; ++mt)
                    mma_tf32(acc[mt][nt], a[mt][0], a[mt][1], a[mt][2], a[mt][3], bf0, bf1);
            }
        }
#pragma unroll
        for (int nt = 0; nt < 2; ++nt) {
            int col0 = warp * 16 + nt * 8 + tig * 2;
            float bb0 = fb2[band * 128 + col0];
            float bb1 = fb2[band * 128 + col0 + 1];
#pragma unroll
            for (int mt = 0; mt < 2; ++mt) {
                int r0 = mt * 16 + grp;
                zs[r0 * ZP + col0]           = __uint_as_float(f2tf(acc[mt][nt][0] + bb0 + hs[r0 * ZP + col0]));
                zs[r0 * ZP + col0 + 1]       = __uint_as_float(f2tf(acc[mt][nt][1] + bb1 + hs[r0 * ZP + col0 + 1]));
                zs[(r0 + 8) * ZP + col0]     = __uint_as_float(f2tf(acc[mt][nt][2] + bb0 + hs[(r0 + 8) * ZP + col0]));
                zs[(r0 + 8) * ZP + col0 + 1] = __uint_as_float(f2tf(acc[mt][nt][3] + bb1 + hs[(r0 + 8) * ZP + col0 + 1]));
            }
        }
    }
    __syncthreads();

    // proj: p = band_out[32,128] @ pw[128,64] + pb -> g_p. warp n-slice 8.
    {
        float acc[2][4];
#pragma unroll
        for (int mt = 0; mt < 2; ++mt)
#pragma unroll
            for (int c = 0; c < 4; ++c) acc[mt][c] = 0.0f;

        const float* pwg = g_wp + (size_t)band * 128 * 64;
        for (int k0 = 0; k0 < 128; k0 += 8) {
            uint32_t a[2][4];
#pragma unroll
            for (int mt = 0; mt < 2; ++mt) {
                int r0 = mt * 16 + grp;
                a[mt][0] = __float_as_uint(zs[r0 * ZP + k0 + tig]);
                a[mt][1] = __float_as_uint(zs[(r0 + 8) * ZP + k0 + tig]);
                a[mt][2] = __float_as_uint(zs[r0 * ZP + k0 + tig + 4]);
                a[mt][3] = __float_as_uint(zs[(r0 + 8) * ZP + k0 + tig + 4]);
            }
            int col = warp * 8 + grp;
            uint32_t bf0 = wld(&pwg[(k0 + tig) * 64 + col]);
            uint32_t bf1 = wld(&pwg[(k0 + tig + 4) * 64 + col]);
#pragma unroll
            for (int mt = 0; mt < 2; ++mt)
                mma_tf32(acc[mt], a[mt][0], a[mt][1], a[mt][2], a[mt][3], bf0, bf1);
        }
        int col0 = warp * 8 + tig * 2;
        float bb0 = pb[band * 64 + col0];
        float bb1 = pb[band * 64 + col0 + 1];
#pragma unroll
        for (int mt = 0; mt < 2; ++mt) {
            int r0 = mt * 16 + grp;
            float2 v0 = make_float2(acc[mt][0] + bb0, acc[mt][1] + bb1);
            float2 v1 = make_float2(acc[mt][2] + bb0, acc[mt][3] + bb1);
            *(float2*)&g_p[(((size_t)b * T_ + t0 + r0) * NB_ + band) * 64 + col0] = v0;
            *(float2*)&g_p[(((size_t)b * T_ + t0 + r0 + 8) * NB_ + band) * 64 + col0] = v1;
        }
    }
}

// ---------------------------------------------------------------------------
// Kernel 3 (tensor-core GEMM1): cat[32,448] @ mix_w1[448,128] -> gelu -> ms
// then fp32 FFMA 128->16. grid (B*T/32), block 256.
// ---------------------------------------------------------------------------
#define CP 452
#define MP 132

__global__ __launch_bounds__(256) void k_mix_tc(
    const float* __restrict__ mb1,
    const float* __restrict__ mw2, const float* __restrict__ mb2,
    float* __restrict__ out)
{
    extern __shared__ float sm[];
    float* cs = sm;                 // 32*452
    float* ms = sm + 32 * CP;       // 32*132

    const int bt0 = blockIdx.x * 32;
    const int tid = threadIdx.x;
    const int warp = tid >> 5, lane = tid & 31;
    const int grp = lane >> 2, tig = lane & 3;

    const float* cb = g_p + (size_t)bt0 * 448;
    for (int i = tid; i < 32 * 448; i += 256) {
        int r = i / 448, c = i - r * 448;
        cs[r * CP + c] = __uint_as_float(f2tf(cb[i]));
    }
    __syncthreads();

    {
        float acc[2][2][4];
#pragma unroll
        for (int mt = 0; mt < 2; ++mt)
#pragma unroll
            for (int nt = 0; nt < 2; ++nt)
#pragma unroll
                for (int c = 0; c < 4; ++c) acc[mt][nt][c] = 0.0f;

        for (int k0 = 0; k0 < 448; k0 += 8) {
            uint32_t a[2][4];
#pragma unroll
            for (int mt = 0; mt < 2; ++mt) {
                int r0 = mt * 16 + grp;
                a[mt][0] = __float_as_uint(cs[r0 * CP + k0 + tig]);
                a[mt][1] = __float_as_uint(cs[(r0 + 8) * CP + k0 + tig]);
                a[mt][2] = __float_as_uint(cs[r0 * CP + k0 + tig + 4]);
                a[mt][3] = __float_as_uint(cs[(r0 + 8) * CP + k0 + tig + 4]);
            }
#pragma unroll
            for (int nt = 0; nt < 2; ++nt) {
                int col = warp * 16 + nt * 8 + grp;
                uint32_t bf0 = wld(&g_wm[(k0 + tig) * 128 + col]);
                uint32_t bf1 = wld(&g_wm[(k0 + tig + 4) * 128 + col]);
#pragma unroll
                for (int mt = 0; mt < 2; ++mt)
                    mma_tf32(acc[mt][nt], a[mt][0], a[mt][1], a[mt][2], a[mt][3], bf0, bf1);
            }
        }
#pragma unroll
        for (int nt = 0; nt < 2; ++nt) {
            int col0 = warp * 16 + nt * 8 + tig * 2;
            float bb0 = mb1[col0];
            float bb1 = mb1[col0 + 1];
#pragma unroll
            for (int mt = 0; mt < 2; ++mt) {
                int r0 = mt * 16 + grp;
                ms[r0 * MP + col0]           = gelu_exact(acc[mt][nt][0] + bb0);
                ms[r0 * MP + col0 + 1]       = gelu_exact(acc[mt][nt][1] + bb1);
                ms[(r0 + 8) * MP + col0]     = gelu_exact(acc[mt][nt][2] + bb0);
                ms[(r0 + 8) * MP + col0 + 1] = gelu_exact(acc[mt][nt][3] + bb1);
            }
        }
    }
    __syncthreads();

    {
        const int o = tid & 15, tb = tid >> 4;
        const float* wc = mw2 + o;
        const float bo = mb2[o];
#pragma unroll
        for (int h = 0; h < 2; ++h) {
            int tt = tb + h * 16;
            float acc = 0.0f;
            for (int e = 0; e < 128; e += 4) {
                float4 mv = *(const float4*)&ms[tt * MP + e];
                acc = fmaf(mv.x, wc[(e + 0) * 16], acc);
                acc = fmaf(mv.y, wc[(e + 1) * 16], acc);
                acc = fmaf(mv.z, wc[(e + 2) * 16], acc);
                acc = fmaf(mv.w, wc[(e + 3) * 16], acc);
            }
            out[(size_t)(bt0 + tt) * 16 + o] = acc + bo;
        }
    }
}

// ---------------------------------------------------------------------------
extern "C" void kernel_launch(void* const* d_in, const int* in_sizes, int n_in,
                              void* d_out, int out_size)
{
    const float* x      = (const float*)d_in[0];
    const float* conv_w = (const float*)d_in[1];
    const float* conv_b = (const float*)d_in[2];
    const float* dec_g  = (const float*)d_in[3];
    const float* dec_b  = (const float*)d_in[4];
    const float* n2_g   = (const float*)d_in[5];
    const float* n2_b   = (const float*)d_in[6];
    const float* ffn_w1 = (const float*)d_in[7];
    const float* ffn_b1 = (const float*)d_in[8];
    const float* ffn_w2 = (const float*)d_in[9];
    const float* ffn_b2 = (const float*)d_in[10];
    const float* proj_w = (const float*)d_in[11];
    const float* proj_b = (const float*)d_in[12];
    const float* mix_w1 = (const float*)d_in[13];
    const float* mix_b1 = (const float*)d_in[14];
    const float* mix_w2 = (const float*)d_in[15];
    const float* mix_b2 = (const float*)d_in[16];
    float* out = (float*)d_out;

    const int smem_ffn = 32 * (ZP * 2 + UP) * 4;            // 67072 B -> 3 CTA/SM
    const int smem_mix = (32 * CP + 32 * MP) * 4;           // 74752 B
    cudaFuncSetAttribute(k_ffn_tc, cudaFuncAttributeMaxDynamicSharedMemorySize, smem_ffn);
    cudaFuncSetAttribute(k_mix_tc, cudaFuncAttributeMaxDynamicSharedMemorySize, smem_mix);

    k_prep<<<512, 256>>>(conv_w, ffn_w1, ffn_w2, proj_w, mix_w1);

    dim3 g1(T_ / 32, B_, NB_);
    k_conv_tc<<<g1, 256>>>(x, conv_b, dec_g, dec_b);

    dim3 g2(T_ / 32, B_, NB_);
    k_ffn_tc<<<g2, 256, smem_ffn>>>(n2_g, n2_b, ffn_b1, ffn_b2, proj_b);

    dim3 g3((B_ * T_) / 32);
    k_mix_tc<<<g3, 256, smem_mix>>>(mix_b1, mix_w2, mix_b2, out);
}

// round 8
// speedup vs baseline: 1.7955x; 1.4240x over previous
#include <cuda_runtime.h>
#include <math.h>
#include <stdint.h>

#define NB_   7
#define S_    16
#define D_    128
#define B_    32
#define T_    2048
#define KMAX_ 31

__constant__ int c_ks[NB_] = {31, 21, 15, 11, 7, 5, 3};

// Scratch (device globals; no allocations allowed)
__device__ float g_h[(size_t)NB_ * B_ * T_ * D_];        // post-LN1 h  [nb][b][t][d]
__device__ float g_p[(size_t)B_ * T_ * NB_ * 4 * S_];    // cat layout  [b][t][nb][4S]

// Fragment-major packed tf32 weights (permuted in k_prep)
#define NWC (NB_ * KMAX_ * S_ * D_)      // 444416
#define NW1 (NB_ * D_ * 2 * D_)          // 229376
#define NW2 (NB_ * 2 * D_ * D_)          // 229376
#define NWP (NB_ * D_ * 64)              // 57344
#define NWM (448 * 128)                  // 57344
__device__ float g_wc[NWC];
__device__ float g_w1[NW1];
__device__ float g_w2[NW2];
__device__ float g_wp[NWP];
__device__ float g_wm[NWM];

__device__ __forceinline__ float gelu_exact(float v) {
    return 0.5f * v * (1.0f + erff(v * 0.70710678118654752440f));
}

__device__ __forceinline__ uint32_t f2tf(float f) {
    uint32_t r;
    asm("cvt.rna.tf32.f32 %0, %1;" : "=r"(r) : "f"(f));
    return r;
}
__device__ __forceinline__ float f2tf_f(float f) { return __uint_as_float(f2tf(f)); }

__device__ __forceinline__ void mma_tf32(float c[4],
    uint32_t a0, uint32_t a1, uint32_t a2, uint32_t a3,
    uint32_t b0, uint32_t b1)
{
    asm volatile(
        "mma.sync.aligned.m16n8k8.row.col.f32.tf32.tf32.f32 "
        "{%0,%1,%2,%3},{%4,%5,%6,%7},{%8,%9},{%0,%1,%2,%3};"
        : "+f"(c[0]), "+f"(c[1]), "+f"(c[2]), "+f"(c[3])
        : "r"(a0), "r"(a1), "r"(a2), "r"(a3), "r"(b0), "r"(b1));
}

// ---------------------------------------------------------------------------
// Kernel 0: tf32-round + permute all GEMM weights into fragment-major order.
// Packed layouts (idx -> source):
//  W1  : idx = ((((band*16+kb)*8+w)*32+lane)*4+nt)*2+pair
//        k = kb*8 + (lane&3) + pair*4 ; col = w*32 + nt*8 + (lane>>2)
//  W2  : idx = ((((band*32+kb)*8+w)*32+lane)*2+nt)*2+pair
//        k = kb*8 + (lane&3) + pair*4 ; col = w*16 + nt*8 + (lane>>2)
//  WP  : idx = ((((band*16+kb)*8+w)*32+lane))*2+pair
//        k = kb*8 + (lane&3) + pair*4 ; col = w*8 + (lane>>2)
//  WC  : idx = (((((band*31+k)*2+c8)*8+w)*32+lane)*2+nt)*2+pair
//        s = c8*8 + (lane&3) + pair*4 ; col = w*16 + nt*8 + (lane>>2)
//  WM  : idx = ((((kb)*8+w)*32+lane)*2+nt)*2+pair
//        k = kb*8 + (lane&3) + pair*4 ; col = w*16 + nt*8 + (lane>>2)
// ---------------------------------------------------------------------------
__global__ __launch_bounds__(256) void k_prep(
    const float* __restrict__ cw, const float* __restrict__ w1,
    const float* __restrict__ w2, const float* __restrict__ pw,
    const float* __restrict__ mw1)
{
    const int stride = gridDim.x * blockDim.x;
    const int i0 = blockIdx.x * blockDim.x + threadIdx.x;

    for (int i = i0; i < NW1; i += stride) {
        int pair = i & 1, nt = (i >> 1) & 3, lane = (i >> 3) & 31;
        int w = (i >> 8) & 7, kb = (i >> 11) & 15, band = i >> 15;
        int k = kb * 8 + (lane & 3) + pair * 4;
        int col = w * 32 + nt * 8 + (lane >> 2);
        g_w1[i] = f2tf_f(w1[((size_t)band * 128 + k) * 256 + col]);
    }
    for (int i = i0; i < NW2; i += stride) {
        int pair = i & 1, nt = (i >> 1) & 1, lane = (i >> 2) & 31;
        int w = (i >> 7) & 7, kb = (i >> 10) & 31, band = i >> 15;
        int k = kb * 8 + (lane & 3) + pair * 4;
        int col = w * 16 + nt * 8 + (lane >> 2);
        g_w2[i] = f2tf_f(w2[((size_t)band * 256 + k) * 128 + col]);
    }
    for (int i = i0; i < NWP; i += stride) {
        int pair = i & 1, lane = (i >> 1) & 31;
        int w = (i >> 6) & 7, kb = (i >> 9) & 15, band = i >> 13;
        int k = kb * 8 + (lane & 3) + pair * 4;
        int col = w * 8 + (lane >> 2);
        g_wp[i] = f2tf_f(pw[((size_t)band * 128 + k) * 64 + col]);
    }
    for (int i = i0; i < NWC; i += stride) {
        int sub = i & 1023;                 // (w,lane,nt,pair)
        int pair = sub & 1, nt = (sub >> 1) & 1, lane = (sub >> 2) & 31, w = sub >> 7;
        int rest = i >> 10;
        int c8 = rest & 1; rest >>= 1;
        int k = rest % 31, band = rest / 31;
        int s = c8 * 8 + (lane & 3) + pair * 4;
        int col = w * 16 + nt * 8 + (lane >> 2);
        g_wc[i] = f2tf_f(cw[(((size_t)band * 31 + k) * 16 + s) * 128 + col]);
    }
    for (int i = i0; i < NWM; i += stride) {
        int pair = i & 1, nt = (i >> 1) & 1, lane = (i >> 2) & 31;
        int w = (i >> 7) & 7, kb = i >> 10;
        int k = kb * 8 + (lane & 3) + pair * 4;
        int col = w * 16 + nt * 8 + (lane >> 2);
        g_wm[i] = f2tf_f(mw1[(size_t)k * 128 + col]);
    }
}

// ---------------------------------------------------------------------------
// Kernel 1 (tensor-core): implicit-GEMM conv (masked taps) + bias + LN -> g_h
// grid (T/32, B, NB), block 256. B-frags via packed float4 loads.
// ---------------------------------------------------------------------------
#define XSTR 20
#define HP   132

__global__ __launch_bounds__(256) void k_conv_tc(
    const float* __restrict__ x,
    const float* __restrict__ conv_b, const float* __restrict__ dec_g,
    const float* __restrict__ dec_b)
{
    __shared__ float xs[(32 + KMAX_ - 1) * XSTR];
    __shared__ float hs[32 * HP];

    const int band = blockIdx.z, b = blockIdx.y;
    const int t0 = blockIdx.x * 32;
    const int tid = threadIdx.x;
    const int warp = tid >> 5, lane = tid & 31;
    const int grp = lane >> 2, tig = lane & 3;

    const float* xb = x + (size_t)b * T_ * S_;
    for (int i = tid; i < 62 * S_; i += 256) {
        int row = i >> 4, s = i & 15;
        int gt = t0 + row - (KMAX_ / 2);
        float v = (gt >= 0 && gt < T_) ? xb[gt * S_ + s] : 0.0f;
        xs[row * XSTR + s] = f2tf_f(v);
    }
    __syncthreads();

    float acc[2][2][4];
#pragma unroll
    for (int mt = 0; mt < 2; ++mt)
#pragma unroll
        for (int nt = 0; nt < 2; ++nt)
#pragma unroll
            for (int c = 0; c < 4; ++c) acc[mt][nt][c] = 0.0f;

    const int Kb = c_ks[band];
    const int off = (KMAX_ - Kb) >> 1;

    for (int k = off; k < off + Kb; ++k) {
#pragma unroll
        for (int c8 = 0; c8 < 2; ++c8) {
            const int s0 = c8 * 8;
            uint32_t a[2][4];
#pragma unroll
            for (int mt = 0; mt < 2; ++mt) {
                int r0 = mt * 16 + grp + k;
                a[mt][0] = __float_as_uint(xs[r0 * XSTR + s0 + tig]);
                a[mt][1] = __float_as_uint(xs[(r0 + 8) * XSTR + s0 + tig]);
                a[mt][2] = __float_as_uint(xs[r0 * XSTR + s0 + tig + 4]);
                a[mt][3] = __float_as_uint(xs[(r0 + 8) * XSTR + s0 + tig + 4]);
            }
            // packed: (((((band*31+k)*2+c8)*8+w)*32+lane)*4)
            const float4 wv = __ldg((const float4*)&g_wc[
                (((((size_t)band * 31 + k) * 2 + c8) * 8 + warp) * 32 + lane) * 4]);
#pragma unroll
            for (int nt = 0; nt < 2; ++nt) {
                uint32_t bf0 = __float_as_uint(nt ? wv.z : wv.x);
                uint32_t bf1 = __float_as_uint(nt ? wv.w : wv.y);
#pragma unroll
                for (int mt = 0; mt < 2; ++mt)
                    mma_tf32(acc[mt][nt], a[mt][0], a[mt][1], a[mt][2], a[mt][3], bf0, bf1);
            }
        }
    }

    // bias -> hs
#pragma unroll
    for (int nt = 0; nt < 2; ++nt) {
        int col0 = warp * 16 + nt * 8 + tig * 2;
        float bb0 = conv_b[band * D_ + col0];
        float bb1 = conv_b[band * D_ + col0 + 1];
#pragma unroll
        for (int mt = 0; mt < 2; ++mt) {
            int r0 = mt * 16 + grp;
            hs[r0 * HP + col0]           = acc[mt][nt][0] + bb0;
            hs[r0 * HP + col0 + 1]       = acc[mt][nt][1] + bb1;
            hs[(r0 + 8) * HP + col0]     = acc[mt][nt][2] + bb0;
            hs[(r0 + 8) * HP + col0 + 1] = acc[mt][nt][3] + bb1;
        }
    }
    __syncthreads();

    // LayerNorm (8 warps x 4 tokens) -> g_h
    {
        float gv[4], bv[4];
#pragma unroll
        for (int c = 0; c < 4; ++c) {
            gv[c] = dec_g[band * D_ + lane + 32 * c];
            bv[c] = dec_b[band * D_ + lane + 32 * c];
        }
        float* hb = g_h + (((size_t)band * B_ + b) * T_ + t0) * D_;
        for (int i = 0; i < 4; ++i) {
            int tt = warp * 4 + i;
            float v[4]; float s = 0.0f;
#pragma unroll
            for (int c = 0; c < 4; ++c) { v[c] = hs[tt * HP + lane + 32 * c]; s += v[c]; }
#pragma unroll
            for (int o = 16; o; o >>= 1) s += __shfl_xor_sync(0xffffffffu, s, o);
            float mean = s * (1.0f / 128.0f);
            float q = 0.0f;
#pragma unroll
            for (int c = 0; c < 4; ++c) { float d0 = v[c] - mean; q = fmaf(d0, d0, q); }
#pragma unroll
            for (int o = 16; o; o >>= 1) q += __shfl_xor_sync(0xffffffffu, q, o);
            float rstd = rsqrtf(q * (1.0f / 128.0f) + 1e-5f);
#pragma unroll
            for (int c = 0; c < 4; ++c)
                hb[(size_t)tt * D_ + lane + 32 * c] = (v[c] - mean) * rstd * gv[c] + bv[c];
        }
    }
}

// ---------------------------------------------------------------------------
// Kernel 2 (tensor-core, 32-token tile, 67KB smem => 3 CTA/SM):
// LN2 -> GEMM1(gelu) -> GEMM2(+h smem) -> proj -> g_p. Packed B loads.
// ---------------------------------------------------------------------------
#define ZP 132
#define UP 260

__global__ __launch_bounds__(256) void k_ffn_tc(
    const float* __restrict__ n2_g, const float* __restrict__ n2_b,
    const float* __restrict__ fb1,
    const float* __restrict__ fb2,
    const float* __restrict__ pb)
{
    extern __shared__ float sm[];
    float* hs = sm;                 // 32*132
    float* zs = sm + 32 * ZP;       // 32*132
    float* us = zs + 32 * ZP;       // 32*260

    const int band = blockIdx.z, b = blockIdx.y;
    const int t0 = blockIdx.x * 32;
    const int tid = threadIdx.x;
    const int warp = tid >> 5, lane = tid & 31;
    const int grp = lane >> 2, tig = lane & 3;

    const float* hbp = g_h + (((size_t)band * B_ + b) * T_ + t0) * 128;
    for (int i = tid; i < 32 * 128; i += 256) {
        int r = i >> 7, c = i & 127;
        hs[r * ZP + c] = hbp[i];
    }
    __syncthreads();

    // LN2: warp handles 4 tokens -> zs (tf32-rounded)
    {
        float gv[4], bv[4];
#pragma unroll
        for (int c = 0; c < 4; ++c) {
            gv[c] = n2_g[band * 128 + lane + 32 * c];
            bv[c] = n2_b[band * 128 + lane + 32 * c];
        }
        for (int i = 0; i < 4; ++i) {
            int tt = warp * 4 + i;
            float v[4]; float s = 0.0f;
#pragma unroll
            for (int c = 0; c < 4; ++c) { v[c] = hs[tt * ZP + lane + 32 * c]; s += v[c]; }
#pragma unroll
            for (int o = 16; o; o >>= 1) s += __shfl_xor_sync(0xffffffffu, s, o);
            float mean = s * (1.0f / 128.0f);
            float q = 0.0f;
#pragma unroll
            for (int c = 0; c < 4; ++c) { float d0 = v[c] - mean; q = fmaf(d0, d0, q); }
#pragma unroll
            for (int o = 16; o; o >>= 1) q += __shfl_xor_sync(0xffffffffu, q, o);
            float rstd = rsqrtf(q * (1.0f / 128.0f) + 1e-5f);
#pragma unroll
            for (int c = 0; c < 4; ++c) {
                float zv = (v[c] - mean) * rstd * gv[c] + bv[c];
                zs[tt * ZP + lane + 32 * c] = f2tf_f(zv);
            }
        }
    }
    __syncthreads();

    // GEMM1: u = gelu(z[32,128] @ W1[128,256] + b1). warp n-slice 32 wide.
    {
        float acc[2][4][4];
#pragma unroll
        for (int mt = 0; mt < 2; ++mt)
#pragma unroll
            for (int nt = 0; nt < 4; ++nt)
#pragma unroll
                for (int c = 0; c < 4; ++c) acc[mt][nt][c] = 0.0f;

        const float* wbase = g_w1 + ((((size_t)band * 16) * 8 + warp) * 32 + lane) * 8;
#pragma unroll 4
        for (int kb = 0; kb < 16; ++kb) {
            int k0 = kb * 8;
            uint32_t a[2][4];
#pragma unroll
            for (int mt = 0; mt < 2; ++mt) {
                int r0 = mt * 16 + grp;
                a[mt][0] = __float_as_uint(zs[r0 * ZP + k0 + tig]);
                a[mt][1] = __float_as_uint(zs[(r0 + 8) * ZP + k0 + tig]);
                a[mt][2] = __float_as_uint(zs[r0 * ZP + k0 + tig + 4]);
                a[mt][3] = __float_as_uint(zs[(r0 + 8) * ZP + k0 + tig + 4]);
            }
            const float4 w0 = __ldg((const float4*)(wbase + (size_t)kb * 2048));
            const float4 w1v = __ldg((const float4*)(wbase + (size_t)kb * 2048 + 4));
            const float wv[8] = {w0.x, w0.y, w0.z, w0.w, w1v.x, w1v.y, w1v.z, w1v.w};
#pragma unroll
            for (int nt = 0; nt < 4; ++nt) {
                uint32_t bf0 = __float_as_uint(wv[nt * 2]);
                uint32_t bf1 = __float_as_uint(wv[nt * 2 + 1]);
#pragma unroll
                for (int mt = 0; mt < 2; ++mt)
                    mma_tf32(acc[mt][nt], a[mt][0], a[mt][1], a[mt][2], a[mt][3], bf0, bf1);
            }
        }
#pragma unroll
        for (int nt = 0; nt < 4; ++nt) {
            int col0 = warp * 32 + nt * 8 + tig * 2;
            float bb0 = fb1[band * 256 + col0];
            float bb1 = fb1[band * 256 + col0 + 1];
#pragma unroll
            for (int mt = 0; mt < 2; ++mt) {
                int r0 = mt * 16 + grp;
                us[r0 * UP + col0]           = f2tf_f(gelu_exact(acc[mt][nt][0] + bb0));
                us[r0 * UP + col0 + 1]       = f2tf_f(gelu_exact(acc[mt][nt][1] + bb1));
                us[(r0 + 8) * UP + col0]     = f2tf_f(gelu_exact(acc[mt][nt][2] + bb0));
                us[(r0 + 8) * UP + col0 + 1] = f2tf_f(gelu_exact(acc[mt][nt][3] + bb1));
            }
        }
    }
    __syncthreads();

    // GEMM2: band_out = h + u[32,256] @ W2[256,128] + b2. warp n-slice 16.
    {
        float acc[2][2][4];
#pragma unroll
        for (int mt = 0; mt < 2; ++mt)
#pragma unroll
            for (int nt = 0; nt < 2; ++nt)
#pragma unroll
                for (int c = 0; c < 4; ++c) acc[mt][nt][c] = 0.0f;

        const float* wbase = g_w2 + ((((size_t)band * 32) * 8 + warp) * 32 + lane) * 4;
#pragma unroll 4
        for (int kb = 0; kb < 32; ++kb) {
            int k0 = kb * 8;
            uint32_t a[2][4];
#pragma unroll
            for (int mt = 0; mt < 2; ++mt) {
                int r0 = mt * 16 + grp;
                a[mt][0] = __float_as_uint(us[r0 * UP + k0 + tig]);
                a[mt][1] = __float_as_uint(us[(r0 + 8) * UP + k0 + tig]);
                a[mt][2] = __float_as_uint(us[r0 * UP + k0 + tig + 4]);
                a[mt][3] = __float_as_uint(us[(r0 + 8) * UP + k0 + tig + 4]);
            }
            const float4 wv = __ldg((const float4*)(wbase + (size_t)kb * 1024));
#pragma unroll
            for (int nt = 0; nt < 2; ++nt) {
                uint32_t bf0 = __float_as_uint(nt ? wv.z : wv.x);
                uint32_t bf1 = __float_as_uint(nt ? wv.w : wv.y);
#pragma unroll
                for (int mt = 0; mt < 2; ++mt)
                    mma_tf32(acc[mt][nt], a[mt][0], a[mt][1], a[mt][2], a[mt][3], bf0, bf1);
            }
        }
#pragma unroll
        for (int nt = 0; nt < 2; ++nt) {
            int col0 = warp * 16 + nt * 8 + tig * 2;
            float bb0 = fb2[band * 128 + col0];
            float bb1 = fb2[band * 128 + col0 + 1];
#pragma unroll
            for (int mt = 0; mt < 2; ++mt) {
                int r0 = mt * 16 + grp;
                zs[r0 * ZP + col0]           = f2tf_f(acc[mt][nt][0] + bb0 + hs[r0 * ZP + col0]);
                zs[r0 * ZP + col0 + 1]       = f2tf_f(acc[mt][nt][1] + bb1 + hs[r0 * ZP + col0 + 1]);
                zs[(r0 + 8) * ZP + col0]     = f2tf_f(acc[mt][nt][2] + bb0 + hs[(r0 + 8) * ZP + col0]);
                zs[(r0 + 8) * ZP + col0 + 1] = f2tf_f(acc[mt][nt][3] + bb1 + hs[(r0 + 8) * ZP + col0 + 1]);
            }
        }
    }
    __syncthreads();

    // proj: p = band_out[32,128] @ pw[128,64] + pb -> g_p. warp n-slice 8.
    {
        float acc[2][4];
#pragma unroll
        for (int mt = 0; mt < 2; ++mt)
#pragma unroll
            for (int c = 0; c < 4; ++c) acc[mt][c] = 0.0f;

        const float* wbase = g_wp + ((((size_t)band * 16) * 8 + warp) * 32 + lane) * 2;
#pragma unroll 4
        for (int kb = 0; kb < 16; ++kb) {
            int k0 = kb * 8;
            uint32_t a[2][4];
#pragma unroll
            for (int mt = 0; mt < 2; ++mt) {
                int r0 = mt * 16 + grp;
                a[mt][0] = __float_as_uint(zs[r0 * ZP + k0 + tig]);
                a[mt][1] = __float_as_uint(zs[(r0 + 8) * ZP + k0 + tig]);
                a[mt][2] = __float_as_uint(zs[r0 * ZP + k0 + tig + 4]);
                a[mt][3] = __float_as_uint(zs[(r0 + 8) * ZP + k0 + tig + 4]);
            }
            const float2 wv = __ldg((const float2*)(wbase + (size_t)kb * 512));
            uint32_t bf0 = __float_as_uint(wv.x);
            uint32_t bf1 = __float_as_uint(wv.y);
#pragma unroll
            for (int mt = 0; mt < 2; ++mt)
                mma_tf32(acc[mt], a[mt][0], a[mt][1], a[mt][2], a[mt][3], bf0, bf1);
        }
        int col0 = warp * 8 + tig * 2;
        float bb0 = pb[band * 64 + col0];
        float bb1 = pb[band * 64 + col0 + 1];
#pragma unroll
        for (int mt = 0; mt < 2; ++mt) {
            int r0 = mt * 16 + grp;
            float2 v0 = make_float2(acc[mt][0] + bb0, acc[mt][1] + bb1);
            float2 v1 = make_float2(acc[mt][2] + bb0, acc[mt][3] + bb1);
            *(float2*)&g_p[(((size_t)b * T_ + t0 + r0) * NB_ + band) * 64 + col0] = v0;
            *(float2*)&g_p[(((size_t)b * T_ + t0 + r0 + 8) * NB_ + band) * 64 + col0] = v1;
        }
    }
}

// ---------------------------------------------------------------------------
// Kernel 3 (tensor-core GEMM1): cat[32,448] @ mix_w1[448,128] -> gelu -> ms
// then fp32 FFMA 128->16. grid (B*T/32), block 256. Packed B loads.
// ---------------------------------------------------------------------------
#define CP 452
#define MP 132

__global__ __launch_bounds__(256) void k_mix_tc(
    const float* __restrict__ mb1,
    const float* __restrict__ mw2, const float* __restrict__ mb2,
    float* __restrict__ out)
{
    extern __shared__ float sm[];
    float* cs = sm;                 // 32*452
    float* ms = sm + 32 * CP;       // 32*132

    const int bt0 = blockIdx.x * 32;
    const int tid = threadIdx.x;
    const int warp = tid >> 5, lane = tid & 31;
    const int grp = lane >> 2, tig = lane & 3;

    const float* cb = g_p + (size_t)bt0 * 448;
    for (int i = tid; i < 32 * 448; i += 256) {
        int r = i / 448, c = i - r * 448;
        cs[r * CP + c] = f2tf_f(cb[i]);
    }
    __syncthreads();

    {
        float acc[2][2][4];
#pragma unroll
        for (int mt = 0; mt < 2; ++mt)
#pragma unroll
            for (int nt = 0; nt < 2; ++nt)
#pragma unroll
                for (int c = 0; c < 4; ++c) acc[mt][nt][c] = 0.0f;

        const float* wbase = g_wm + ((size_t)warp * 32 + lane) * 4;
#pragma unroll 4
        for (int kb = 0; kb < 56; ++kb) {
            int k0 = kb * 8;
            uint32_t a[2][4];
#pragma unroll
            for (int mt = 0; mt < 2; ++mt) {
                int r0 = mt * 16 + grp;
                a[mt][0] = __float_as_uint(cs[r0 * CP + k0 + tig]);
                a[mt][1] = __float_as_uint(cs[(r0 + 8) * CP + k0 + tig]);
                a[mt][2] = __float_as_uint(cs[r0 * CP + k0 + tig + 4]);
                a[mt][3] = __float_as_uint(cs[(r0 + 8) * CP + k0 + tig + 4]);
            }
            const float4 wv = __ldg((const float4*)(wbase + (size_t)kb * 1024));
#pragma unroll
            for (int nt = 0; nt < 2; ++nt) {
                uint32_t bf0 = __float_as_uint(nt ? wv.z : wv.x);
                uint32_t bf1 = __float_as_uint(nt ? wv.w : wv.y);
#pragma unroll
                for (int mt = 0; mt < 2; ++mt)
                    mma_tf32(acc[mt][nt], a[mt][0], a[mt][1], a[mt][2], a[mt][3], bf0, bf1);
            }
        }
#pragma unroll
        for (int nt = 0; nt < 2; ++nt) {
            int col0 = warp * 16 + nt * 8 + tig * 2;
            float bb0 = mb1[col0];
            float bb1 = mb1[col0 + 1];
#pragma unroll
            for (int mt = 0; mt < 2; ++mt) {
                int r0 = mt * 16 + grp;
                ms[r0 * MP + col0]           = gelu_exact(acc[mt][nt][0] + bb0);
                ms[r0 * MP + col0 + 1]       = gelu_exact(acc[mt][nt][1] + bb1);
                ms[(r0 + 8) * MP + col0]     = gelu_exact(acc[mt][nt][2] + bb0);
                ms[(r0 + 8) * MP + col0 + 1] = gelu_exact(acc[mt][nt][3] + bb1);
            }
        }
    }
    __syncthreads();

    {
        const int o = tid & 15, tb = tid >> 4;
        const float* wc = mw2 + o;
        const float bo = mb2[o];
#pragma unroll
        for (int h = 0; h < 2; ++h) {
            int tt = tb + h * 16;
            float acc = 0.0f;
            for (int e = 0; e < 128; e += 4) {
                float4 mv = *(const float4*)&ms[tt * MP + e];
                acc = fmaf(mv.x, wc[(e + 0) * 16], acc);
                acc = fmaf(mv.y, wc[(e + 1) * 16], acc);
                acc = fmaf(mv.z, wc[(e + 2) * 16], acc);
                acc = fmaf(mv.w, wc[(e + 3) * 16], acc);
            }
            out[(size_t)(bt0 + tt) * 16 + o] = acc + bo;
        }
    }
}

// ---------------------------------------------------------------------------
extern "C" void kernel_launch(void* const* d_in, const int* in_sizes, int n_in,
                              void* d_out, int out_size)
{
    const float* x      = (const float*)d_in[0];
    const float* conv_w = (const float*)d_in[1];
    const float* conv_b = (const float*)d_in[2];
    const float* dec_g  = (const float*)d_in[3];
    const float* dec_b  = (const float*)d_in[4];
    const float* n2_g   = (const float*)d_in[5];
    const float* n2_b   = (const float*)d_in[6];
    const float* ffn_w1 = (const float*)d_in[7];
    const float* ffn_b1 = (const float*)d_in[8];
    const float* ffn_w2 = (const float*)d_in[9];
    const float* ffn_b2 = (const float*)d_in[10];
    const float* proj_w = (const float*)d_in[11];
    const float* proj_b = (const float*)d_in[12];
    const float* mix_w1 = (const float*)d_in[13];
    const float* mix_b1 = (const float*)d_in[14];
    const float* mix_w2 = (const float*)d_in[15];
    const float* mix_b2 = (const float*)d_in[16];
    float* out = (float*)d_out;

    const int smem_ffn = 32 * (ZP * 2 + UP) * 4;            // 67072 B -> 3 CTA/SM
    const int smem_mix = (32 * CP + 32 * MP) * 4;           // 74752 B
    cudaFuncSetAttribute(k_ffn_tc, cudaFuncAttributeMaxDynamicSharedMemorySize, smem_ffn);
    cudaFuncSetAttribute(k_mix_tc, cudaFuncAttributeMaxDynamicSharedMemorySize, smem_mix);

    k_prep<<<512, 256>>>(conv_w, ffn_w1, ffn_w2, proj_w, mix_w1);

    dim3 g1(T_ / 32, B_, NB_);
    k_conv_tc<<<g1, 256>>>(x, conv_b, dec_g, dec_b);

    dim3 g2(T_ / 32, B_, NB_);
    k_ffn_tc<<<g2, 256, smem_ffn>>>(n2_g, n2_b, ffn_b1, ffn_b2, proj_b);

    dim3 g3((B_ * T_) / 32);
    k_mix_tc<<<g3, 256, smem_mix>>>(mix_b1, mix_w2, mix_b2, out);
}